// round 1
// baseline (speedup 1.0000x reference)
#include <cuda_runtime.h>
#include <math.h>

// TreeLSTM_20658792693767 — round 1: correct fp32 baseline, clean pipeline.
//
// Inputs (metadata order):
//  0 child_hs   f32 [E, 256]
//  1 child_cs   f32 [E, 256]
//  2 segment_ids i32 [E]   (sorted ascending)
//  3 num_segments (device scalar, unused — P derived from out_size)
//  4 W_gates    f32 [256, 768]
//  5 b_gates    f32 [768]
//  6 W_f        f32 [256, 256]
//  7 b_f        f32 [256]
// Output: h [P,256] then c [P,256]  (out_size = 2*P*256)

#define D   256
#define D3  768
#define MAX_P 100000

// Scratch (no allocation allowed): segment sums and fc accumulator.
__device__ float g_hs_sum[(size_t)MAX_P * D];
__device__ float g_fc[(size_t)MAX_P * D];

__device__ __forceinline__ float sigmoid_f(float x) {
    return 1.0f / (1.0f + __expf(-x));
}

// ---------------------------------------------------------------------------
// K1: per-parent segment sum of child_hs.  One CTA per parent, 256 threads.
// Child range found by binary search on the sorted segment_ids.
// ---------------------------------------------------------------------------
__global__ void k_hs_sum(const float* __restrict__ hs,
                         const int*   __restrict__ seg,
                         int E,
                         float* __restrict__ out) {
    __shared__ int sb[2];
    int p = blockIdx.x;
    if (threadIdx.x < 2) {
        int target = p + (int)threadIdx.x;
        int lo = 0, hi = E;
        while (lo < hi) {
            int m = (lo + hi) >> 1;
            if (seg[m] < target) lo = m + 1; else hi = m;
        }
        sb[threadIdx.x] = lo;
    }
    __syncthreads();
    int lo = sb[0], hi = sb[1];
    float s = 0.0f;
    for (int e = lo; e < hi; ++e)
        s += hs[(size_t)e * D + threadIdx.x];
    out[(size_t)p * D + threadIdx.x] = s;
}

// ---------------------------------------------------------------------------
// K2: gates GEMM.  C = hs_sum[P,256] @ W_gates[256,768] + b, with the three
// 256-wide column groups (i, o, g) computed together per tile so the
// activation combine fuses in the epilogue.
// Tile: BM=64, BN=32 (per gate), BK=16. 256 threads, micro 4x2 per gate.
// Writes: out_c <- sigmoid(i)*tanh(g),  out_h <- sigmoid(o)
// ---------------------------------------------------------------------------
__global__ void k_gates(const float* __restrict__ A,   // [P, 256]
                        const float* __restrict__ W,   // [256, 768]
                        const float* __restrict__ b,   // [768]
                        float* __restrict__ out_h,     // [P, 256] <- o
                        float* __restrict__ out_c,     // [P, 256] <- i*g
                        int P) {
    __shared__ float As[16][65];       // [k][m]
    __shared__ float Bs[3][16][33];    // [gate][k][n]

    int bm = blockIdx.x * 64;
    int bn = blockIdx.y * 32;
    int tid = threadIdx.x;
    int tx = tid & 15;      // col group (2 cols)
    int ty = tid >> 4;      // row group (4 rows)

    float acc[3][4][2];
    #pragma unroll
    for (int g = 0; g < 3; ++g)
        #pragma unroll
        for (int i = 0; i < 4; ++i) { acc[g][i][0] = 0.f; acc[g][i][1] = 0.f; }

    for (int kk = 0; kk < D; kk += 16) {
        // A tile: 64 rows x 16 k
        #pragma unroll
        for (int idx = tid; idx < 64 * 16; idx += 256) {
            int r = idx >> 4, k = idx & 15;
            int row = bm + r;
            As[k][r] = (row < P) ? A[(size_t)row * D + kk + k] : 0.0f;
        }
        // B tiles: 3 gates x 16 k x 32 n
        #pragma unroll
        for (int idx = tid; idx < 16 * 96; idx += 256) {
            int k = idx / 96, c = idx % 96;
            int gate = c >> 5, n = c & 31;
            Bs[gate][k][n] = W[(size_t)(kk + k) * D3 + gate * 256 + bn + n];
        }
        __syncthreads();

        #pragma unroll
        for (int k = 0; k < 16; ++k) {
            float a0 = As[k][ty * 4 + 0];
            float a1 = As[k][ty * 4 + 1];
            float a2 = As[k][ty * 4 + 2];
            float a3 = As[k][ty * 4 + 3];
            #pragma unroll
            for (int g = 0; g < 3; ++g) {
                float w0 = Bs[g][k][tx * 2 + 0];
                float w1 = Bs[g][k][tx * 2 + 1];
                acc[g][0][0] += a0 * w0;  acc[g][0][1] += a0 * w1;
                acc[g][1][0] += a1 * w0;  acc[g][1][1] += a1 * w1;
                acc[g][2][0] += a2 * w0;  acc[g][2][1] += a2 * w1;
                acc[g][3][0] += a3 * w0;  acc[g][3][1] += a3 * w1;
            }
        }
        __syncthreads();
    }

    #pragma unroll
    for (int i = 0; i < 4; ++i) {
        int row = bm + ty * 4 + i;
        if (row >= P) continue;
        #pragma unroll
        for (int j = 0; j < 2; ++j) {
            int n = bn + tx * 2 + j;
            float vi = sigmoid_f(acc[0][i][j] + b[n]);
            float vo = sigmoid_f(acc[1][i][j] + b[256 + n]);
            float vg = tanhf(acc[2][i][j] + b[512 + n]);
            out_c[(size_t)row * D + n] = vi * vg;
            out_h[(size_t)row * D + n] = vo;
        }
    }
}

// ---------------------------------------------------------------------------
// K3: forget-gate GEMM over children + fused segment reduce.
// f = sigmoid(child_hs @ W_f + b_f); fc[seg] += f * child_cs.
// Tile: BM=64, BN=64, BK=16. 256 threads, micro 4x4. Thread rows are
// CONTIGUOUS so sorted segment ids merge before atomicAdd (fewer REDG).
// ---------------------------------------------------------------------------
__global__ void k_fgemm(const float* __restrict__ A,   // child_hs [E,256]
                        const float* __restrict__ CC,  // child_cs [E,256]
                        const int*   __restrict__ seg, // [E]
                        const float* __restrict__ W,   // W_f [256,256]
                        const float* __restrict__ b,   // [256]
                        float* __restrict__ fc,        // [P,256] (pre-zeroed)
                        int E) {
    __shared__ float As[16][65];   // [k][m]
    __shared__ float Bs[16][65];   // [k][n]

    int bm = blockIdx.x * 64;
    int bn = blockIdx.y * 64;
    int tid = threadIdx.x;
    int tx = tid & 15;   // 4 cols
    int ty = tid >> 4;   // 4 contiguous rows

    float acc[4][4];
    #pragma unroll
    for (int i = 0; i < 4; ++i)
        #pragma unroll
        for (int j = 0; j < 4; ++j) acc[i][j] = 0.f;

    for (int kk = 0; kk < D; kk += 16) {
        #pragma unroll
        for (int idx = tid; idx < 64 * 16; idx += 256) {
            int r = idx >> 4, k = idx & 15;
            int row = bm + r;
            As[k][r] = (row < E) ? A[(size_t)row * D + kk + k] : 0.0f;
        }
        #pragma unroll
        for (int idx = tid; idx < 16 * 64; idx += 256) {
            int k = idx >> 6, n = idx & 63;
            Bs[k][n] = W[(size_t)(kk + k) * D + bn + n];
        }
        __syncthreads();

        #pragma unroll
        for (int k = 0; k < 16; ++k) {
            float a0 = As[k][ty * 4 + 0];
            float a1 = As[k][ty * 4 + 1];
            float a2 = As[k][ty * 4 + 2];
            float a3 = As[k][ty * 4 + 3];
            float w0 = Bs[k][tx * 4 + 0];
            float w1 = Bs[k][tx * 4 + 1];
            float w2 = Bs[k][tx * 4 + 2];
            float w3 = Bs[k][tx * 4 + 3];
            acc[0][0] += a0 * w0; acc[0][1] += a0 * w1; acc[0][2] += a0 * w2; acc[0][3] += a0 * w3;
            acc[1][0] += a1 * w0; acc[1][1] += a1 * w1; acc[1][2] += a1 * w2; acc[1][3] += a1 * w3;
            acc[2][0] += a2 * w0; acc[2][1] += a2 * w1; acc[2][2] += a2 * w2; acc[2][3] += a2 * w3;
            acc[3][0] += a3 * w0; acc[3][1] += a3 * w1; acc[3][2] += a3 * w2; acc[3][3] += a3 * w3;
        }
        __syncthreads();
    }

    // Epilogue: sigmoid + *cc, merge contiguous equal segments, atomicAdd.
    int rows[4], gs[4];
    #pragma unroll
    for (int i = 0; i < 4; ++i) {
        rows[i] = bm + ty * 4 + i;
        gs[i] = (rows[i] < E) ? seg[rows[i]] : -1;
    }
    #pragma unroll
    for (int j = 0; j < 4; ++j) {
        int n = bn + tx * 4 + j;
        float bias = b[n];
        float run = 0.0f;
        int cur = gs[0];
        #pragma unroll
        for (int i = 0; i < 4; ++i) {
            if (gs[i] != cur) {
                if (cur >= 0) atomicAdd(&fc[(size_t)cur * D + n], run);
                cur = gs[i];
                run = 0.0f;
            }
            if (gs[i] >= 0) {
                float f = sigmoid_f(acc[i][j] + bias);
                run += f * CC[(size_t)rows[i] * D + n];
            }
        }
        if (cur >= 0) atomicAdd(&fc[(size_t)cur * D + n], run);
    }
}

// ---------------------------------------------------------------------------
// K4: final combine.  out_c holds i*g, out_h holds o (from K2).
// c = i*g + fc ; h = o * tanh(c)
// ---------------------------------------------------------------------------
__global__ void k_final(const float* __restrict__ fc,
                        float* __restrict__ out,   // [2*P*256]: h then c
                        int total) {               // total = P*256
    int idx = blockIdx.x * blockDim.x + threadIdx.x;
    if (idx < total) {
        float ig = out[(size_t)total + idx];
        float o  = out[idx];
        float c  = ig + fc[idx];
        out[(size_t)total + idx] = c;
        out[idx] = o * tanhf(c);
    }
}

// ---------------------------------------------------------------------------
extern "C" void kernel_launch(void* const* d_in, const int* in_sizes, int n_in,
                              void* d_out, int out_size) {
    const float* child_hs = (const float*)d_in[0];
    const float* child_cs = (const float*)d_in[1];
    const int*   seg      = (const int*)d_in[2];
    // d_in[3] = num_segments (device scalar) — P derived from out_size instead
    const float* Wg = (const float*)d_in[4];
    const float* bg = (const float*)d_in[5];
    const float* Wf = (const float*)d_in[6];
    const float* bf = (const float*)d_in[7];
    (void)n_in;

    int E = in_sizes[2];             // number of child edges
    int P = out_size / (2 * D);      // number of parents
    if (P > MAX_P) P = MAX_P;        // scratch bound (P is 100000 in this problem)

    float* out   = (float*)d_out;
    float* out_h = out;                    // h region (scratch: o)
    float* out_c = out + (size_t)P * D;    // c region (scratch: i*g)

    static float* fc_ptr = nullptr;
    static float* hs_ptr = nullptr;
    if (!fc_ptr) {
        cudaGetSymbolAddress((void**)&fc_ptr, g_fc);
        cudaGetSymbolAddress((void**)&hs_ptr, g_hs_sum);
    }

    // fc accumulator must be zero at every (graph-replayed) invocation.
    cudaMemsetAsync(fc_ptr, 0, (size_t)P * D * sizeof(float), 0);

    // K1: segment sum of child_hs
    k_hs_sum<<<P, 256>>>(child_hs, seg, E, hs_ptr);

    // K2: gates GEMM + activations (writes o -> out_h, i*g -> out_c)
    dim3 g2((P + 63) / 64, D / 32);
    k_gates<<<g2, 256>>>(hs_ptr, Wg, bg, out_h, out_c, P);

    // K3: forget GEMM + fused segment reduce into fc
    dim3 g3((E + 63) / 64, D / 64);
    k_fgemm<<<g3, 256>>>(child_hs, child_cs, seg, Wf, bf, fc_ptr, E);

    // K4: final LSTM combine (in place over d_out)
    k_final<<<(P * D + 255) / 256, 256>>>(fc_ptr, out, P * D);
}

// round 3
// speedup vs baseline: 2.6556x; 2.6556x over previous
#include <cuda_runtime.h>
#include <cuda_bf16.h>
#include <math.h>
#include <stdint.h>

// TreeLSTM — round 3: warp-level HMMA (mma.sync bf16, 3-pass hi/lo split).
// tcgen05 is unavailable: harness device pass targets plain sm_103 (no 'a').
//
// Pipeline:
//  k_wsplit : W_f, W_gates -> transposed [N][K] bf16 hi/lo
//  k_hs_sum : per-parent segment sum of child_hs -> bf16 hi/lo [P][256]
//  k_gemm<0>: fcprod[e] = sigmoid(child_hs@W_f^T + b_f) * child_cs   (per edge)
//  k_gemm<1>: gates: sig(i)->g_iact, sig(o)->out_h, tanh(g)->g_gact
//  k_final  : fc = segsum(fcprod); c = i*g + fc; h = o*tanh(c)

#define D    256
#define D3   768
#define MAX_P 100000
#define MAX_E 400000

// ---------------- scratch (static __device__, no allocation) ----------------
__device__ float g_fcprod[(size_t)MAX_E * D];
__device__ float g_iact[(size_t)MAX_P * D];
__device__ float g_gact[(size_t)MAX_P * D];
__device__ __nv_bfloat16 g_hshi[(size_t)MAX_P * D];
__device__ __nv_bfloat16 g_hslo[(size_t)MAX_P * D];
__device__ __nv_bfloat16 g_wf_hi[D * D];
__device__ __nv_bfloat16 g_wf_lo[D * D];
__device__ __nv_bfloat16 g_wg_hi[D3 * D];
__device__ __nv_bfloat16 g_wg_lo[D3 * D];

// ---------------- helpers ----------------
__device__ __forceinline__ uint32_t smem_to_u32(const void* p) {
    uint32_t a;
    asm("{ .reg .u64 t; cvta.to.shared.u64 t, %1; cvt.u32.u64 %0, t; }" : "=r"(a) : "l"(p));
    return a;
}
__device__ __forceinline__ float sigmoid_f(float x) { return 1.0f / (1.0f + __expf(-x)); }
__device__ __forceinline__ uint32_t pack_bf16(__nv_bfloat16 a, __nv_bfloat16 b) {
    return (uint32_t)__bfloat16_as_ushort(a) | ((uint32_t)__bfloat16_as_ushort(b) << 16);
}

#define CP_ASYNC16(dst, src) \
    asm volatile("cp.async.cg.shared.global [%0], [%1], 16;" :: "r"(dst), "l"(src))
#define CP_COMMIT() asm volatile("cp.async.commit_group;")
#define CP_WAIT_ALL() asm volatile("cp.async.wait_group 0;")

__device__ __forceinline__ void ldsm_x4(uint32_t a[4], uint32_t addr) {
    asm volatile("ldmatrix.sync.aligned.m8n8.x4.shared.b16 {%0,%1,%2,%3}, [%4];"
        : "=r"(a[0]), "=r"(a[1]), "=r"(a[2]), "=r"(a[3]) : "r"(addr));
}
__device__ __forceinline__ void ldsm_x2(uint32_t b[2], uint32_t addr) {
    asm volatile("ldmatrix.sync.aligned.m8n8.x2.shared.b16 {%0,%1}, [%2];"
        : "=r"(b[0]), "=r"(b[1]) : "r"(addr));
}
__device__ __forceinline__ void mma_bf16(float c[4], const uint32_t a[4], const uint32_t b[2]) {
    asm volatile(
        "mma.sync.aligned.m16n8k16.row.col.f32.bf16.bf16.f32 "
        "{%0,%1,%2,%3}, {%4,%5,%6,%7}, {%8,%9}, {%0,%1,%2,%3};"
        : "+f"(c[0]), "+f"(c[1]), "+f"(c[2]), "+f"(c[3])
        : "r"(a[0]), "r"(a[1]), "r"(a[2]), "r"(a[3]), "r"(b[0]), "r"(b[1]));
}

// Swizzled byte offset inside a [rows][32 bf16] tile (64B rows, 4x16B chunks).
// chunk ^= (row>>1)&3 makes 8 consecutive rows hit 8 distinct 16B bank slots.
__device__ __forceinline__ uint32_t swz(int row, int ch) {
    return (uint32_t)(row * 64 + ((ch ^ ((row >> 1) & 3)) << 4));
}

// ---------------------------------------------------------------------------
// k_wsplit: W[256 x ncols] row-major -> T_hi/T_lo [ncols][256] bf16
// ---------------------------------------------------------------------------
__global__ void k_wsplit(const float* __restrict__ W, int ncols,
                         __nv_bfloat16* __restrict__ Thi,
                         __nv_bfloat16* __restrict__ Tlo) {
    __shared__ float s[32][33];
    int nt = blockIdx.x * 32, kt = blockIdx.y * 32;
    int tx = threadIdx.x & 31, ty = threadIdx.x >> 5;
    #pragma unroll
    for (int i = 0; i < 4; ++i)
        s[ty + i * 8][tx] = W[(size_t)(kt + ty + i * 8) * ncols + nt + tx];
    __syncthreads();
    #pragma unroll
    for (int i = 0; i < 4; ++i) {
        int n = nt + ty + i * 8;
        int k = kt + tx;
        float x = s[tx][ty + i * 8];
        __nv_bfloat16 hi = __float2bfloat16_rn(x);
        __nv_bfloat16 lo = __float2bfloat16_rn(x - __bfloat162float(hi));
        Thi[(size_t)n * D + k] = hi;
        Tlo[(size_t)n * D + k] = lo;
    }
}

// ---------------------------------------------------------------------------
// k_hs_sum: per-parent segment sum of child_hs -> bf16 hi/lo
// ---------------------------------------------------------------------------
__global__ void k_hs_sum(const float* __restrict__ hs, const int* __restrict__ seg,
                         int E, __nv_bfloat16* __restrict__ ohi,
                         __nv_bfloat16* __restrict__ olo) {
    __shared__ int sb2[2];
    int p = blockIdx.x;
    if (threadIdx.x < 2) {
        int target = p + (int)threadIdx.x;
        int lo = 0, hi = E;
        while (lo < hi) { int m = (lo + hi) >> 1; if (seg[m] < target) lo = m + 1; else hi = m; }
        sb2[threadIdx.x] = lo;
    }
    __syncthreads();
    int lo = sb2[0], hi = sb2[1];
    float s = 0.0f;
    for (int e = lo; e < hi; ++e) s += hs[(size_t)e * D + threadIdx.x];
    __nv_bfloat16 h = __float2bfloat16_rn(s);
    __nv_bfloat16 l = __float2bfloat16_rn(s - __bfloat162float(h));
    ohi[(size_t)p * D + threadIdx.x] = h;
    olo[(size_t)p * D + threadIdx.x] = l;
}

// ---------------------------------------------------------------------------
// k_gemm<MODE>: HMMA bf16-split GEMM. CTA tile M=64 x N=256, BK=32, 8 chunks.
// MODE 0: A fp32 (inline split). out: o0[row] = sigmoid(acc+bias)*cc[row]
// MODE 1: A bf16 hi/lo in gmem. gate = blockIdx.y; o0/o1/o2 per gate.
// ---------------------------------------------------------------------------
#define SM_AHI 0
#define SM_ALO 4096
#define SM_BHI 8192
#define SM_BLO 24576
#define SM_STAGE 40960
#define SM_TOTAL (2 * SM_STAGE)

template <int MODE>
__global__ void __launch_bounds__(256, 2)
k_gemm(const float* __restrict__ A32,
       const __nv_bfloat16* __restrict__ Ahi_g,
       const __nv_bfloat16* __restrict__ Alo_g,
       const __nv_bfloat16* __restrict__ Bhi_g,
       const __nv_bfloat16* __restrict__ Blo_g,
       const float* __restrict__ bias_g,
       const float* __restrict__ cc,
       float* __restrict__ o0, float* __restrict__ o1, float* __restrict__ o2,
       int Mtot) {
    extern __shared__ char smem[];
    const uint32_t sb = smem_to_u32(smem);
    const int tid  = threadIdx.x;
    const int lane = tid & 31;
    const int wid  = tid >> 5;
    const int bm   = blockIdx.x * 64;
    const int gate = (MODE == 1) ? (int)blockIdx.y : 0;

    const __nv_bfloat16* Bhi = Bhi_g + (size_t)gate * 256 * D;
    const __nv_bfloat16* Blo = Blo_g + (size_t)gate * 256 * D;
    const float* bias = bias_g + gate * 256;

    float acc[2][8][4];
    #pragma unroll
    for (int i = 0; i < 2; ++i)
        #pragma unroll
        for (int j = 0; j < 8; ++j)
            #pragma unroll
            for (int q = 0; q < 4; ++q) acc[i][j][q] = 0.f;

    // staging geometry: A chunk per thread (row = tid>>2, 16B chunk = tid&3)
    const int arow = tid >> 2;
    const int achk = tid & 3;
    const int arow_g = min(bm + arow, Mtot - 1);    // clamp: extra rows never stored
    const uint32_t aoff = swz(arow, achk);

    float4 af0, af1;

    // ---- staging helpers as macros ----
#define LDG_A0(kc) do { \
        const float* _p = A32 + (size_t)arow_g * D + (kc) * 32 + achk * 8; \
        af0 = *(const float4*)_p; af1 = *(const float4*)(_p + 4); \
    } while (0)

#define STS_A0(buf) do { \
        __nv_bfloat16 h0 = __float2bfloat16_rn(af0.x), h1 = __float2bfloat16_rn(af0.y); \
        __nv_bfloat16 h2 = __float2bfloat16_rn(af0.z), h3 = __float2bfloat16_rn(af0.w); \
        __nv_bfloat16 h4 = __float2bfloat16_rn(af1.x), h5 = __float2bfloat16_rn(af1.y); \
        __nv_bfloat16 h6 = __float2bfloat16_rn(af1.z), h7 = __float2bfloat16_rn(af1.w); \
        __nv_bfloat16 l0 = __float2bfloat16_rn(af0.x - __bfloat162float(h0)); \
        __nv_bfloat16 l1 = __float2bfloat16_rn(af0.y - __bfloat162float(h1)); \
        __nv_bfloat16 l2 = __float2bfloat16_rn(af0.z - __bfloat162float(h2)); \
        __nv_bfloat16 l3 = __float2bfloat16_rn(af0.w - __bfloat162float(h3)); \
        __nv_bfloat16 l4 = __float2bfloat16_rn(af1.x - __bfloat162float(h4)); \
        __nv_bfloat16 l5 = __float2bfloat16_rn(af1.y - __bfloat162float(h5)); \
        __nv_bfloat16 l6 = __float2bfloat16_rn(af1.z - __bfloat162float(h6)); \
        __nv_bfloat16 l7 = __float2bfloat16_rn(af1.w - __bfloat162float(h7)); \
        uint4 uh = make_uint4(pack_bf16(h0,h1), pack_bf16(h2,h3), pack_bf16(h4,h5), pack_bf16(h6,h7)); \
        uint4 ul = make_uint4(pack_bf16(l0,l1), pack_bf16(l2,l3), pack_bf16(l4,l5), pack_bf16(l6,l7)); \
        *(uint4*)(smem + (buf) + SM_AHI + aoff) = uh; \
        *(uint4*)(smem + (buf) + SM_ALO + aoff) = ul; \
    } while (0)

#define STAGE_A1(kc, buf) do { \
        const __nv_bfloat16* _sh = Ahi_g + (size_t)arow_g * D + (kc) * 32 + achk * 8; \
        const __nv_bfloat16* _sl = Alo_g + (size_t)arow_g * D + (kc) * 32 + achk * 8; \
        CP_ASYNC16(sb + (buf) + SM_AHI + aoff, _sh); \
        CP_ASYNC16(sb + (buf) + SM_ALO + aoff, _sl); \
    } while (0)

#define STAGE_B(kc, buf) do { \
        _Pragma("unroll") \
        for (int _it = 0; _it < 4; ++_it) { \
            int _c = tid + _it * 256; int _n = _c >> 2; int _ch = _c & 3; \
            uint32_t _off = swz(_n, _ch); \
            CP_ASYNC16(sb + (buf) + SM_BHI + _off, Bhi + (size_t)_n * D + (kc) * 32 + _ch * 8); \
            CP_ASYNC16(sb + (buf) + SM_BLO + _off, Blo + (size_t)_n * D + (kc) * 32 + _ch * 8); \
        } \
    } while (0)

    // ---- preamble: stage chunk 0 ----
    if (MODE == 0) { LDG_A0(0); } else { STAGE_A1(0, 0); }
    STAGE_B(0, 0);
    CP_COMMIT();
    if (MODE == 0) STS_A0(0);
    CP_WAIT_ALL();
    __syncthreads();

    const int mbase = (wid >> 2) * 32;
    const int nbw   = (wid & 3) * 64;
    const int arl = lane & 15;
    const int ach_half = lane >> 4;
    const int brl = lane & 7;
    const int bch_half = (lane >> 3) & 1;

    for (int kc = 0; kc < 8; ++kc) {
        const uint32_t buf  = (uint32_t)((kc & 1) * SM_STAGE);
        const uint32_t nbuf = (uint32_t)(((kc + 1) & 1) * SM_STAGE);
        if (kc < 7) {
            if (MODE == 0) { LDG_A0(kc + 1); } else { STAGE_A1(kc + 1, nbuf); }
            STAGE_B(kc + 1, nbuf);
            CP_COMMIT();
        }

        // ---- compute current chunk: 3 split passes over 2 k16 steps ----
        {
            const uint32_t base = sb + buf;
            uint32_t ah[2][4], al[2][4], bb[8][2];
            #pragma unroll
            for (int s = 0; s < 2; ++s) {
                #pragma unroll
                for (int mf = 0; mf < 2; ++mf) {
                    int r = mbase + mf * 16 + arl;
                    int ch = s * 2 + ach_half;
                    uint32_t o = swz(r, ch);
                    ldsm_x4(ah[mf], base + SM_AHI + o);
                    ldsm_x4(al[mf], base + SM_ALO + o);
                }
                #pragma unroll
                for (int nf = 0; nf < 8; ++nf) {
                    int r = nbw + nf * 8 + brl;
                    int ch = s * 2 + bch_half;
                    ldsm_x2(bb[nf], base + SM_BHI + swz(r, ch));
                }
                #pragma unroll
                for (int mf = 0; mf < 2; ++mf)
                    #pragma unroll
                    for (int nf = 0; nf < 8; ++nf) mma_bf16(acc[mf][nf], ah[mf], bb[nf]);
                #pragma unroll
                for (int mf = 0; mf < 2; ++mf)
                    #pragma unroll
                    for (int nf = 0; nf < 8; ++nf) mma_bf16(acc[mf][nf], al[mf], bb[nf]);
                #pragma unroll
                for (int nf = 0; nf < 8; ++nf) {
                    int r = nbw + nf * 8 + brl;
                    int ch = s * 2 + bch_half;
                    ldsm_x2(bb[nf], base + SM_BLO + swz(r, ch));
                }
                #pragma unroll
                for (int mf = 0; mf < 2; ++mf)
                    #pragma unroll
                    for (int nf = 0; nf < 8; ++nf) mma_bf16(acc[mf][nf], ah[mf], bb[nf]);
            }
        }

        if (MODE == 0 && kc < 7) STS_A0(nbuf);
        CP_WAIT_ALL();
        __syncthreads();
    }

    // ---- epilogue: bias + activation, direct register stores ----
    #pragma unroll
    for (int mf = 0; mf < 2; ++mf) {
        #pragma unroll
        for (int nf = 0; nf < 8; ++nf) {
            int cn = nbw + nf * 8 + 2 * (lane & 3);
            float b0 = __ldg(bias + cn), b1 = __ldg(bias + cn + 1);
            #pragma unroll
            for (int half = 0; half < 2; ++half) {
                int r = bm + mbase + mf * 16 + (lane >> 2) + half * 8;
                if (r < Mtot) {
                    float v0 = acc[mf][nf][half * 2 + 0] + b0;
                    float v1 = acc[mf][nf][half * 2 + 1] + b1;
                    size_t o = (size_t)r * D + cn;
                    if (MODE == 0) {
                        float2 ccv = *(const float2*)(cc + o);
                        float2 res = make_float2(sigmoid_f(v0) * ccv.x, sigmoid_f(v1) * ccv.y);
                        *(float2*)(o0 + o) = res;
                    } else {
                        float r0, r1;
                        if (gate == 2) { r0 = tanhf(v0); r1 = tanhf(v1); }
                        else           { r0 = sigmoid_f(v0); r1 = sigmoid_f(v1); }
                        float* op = (gate == 0) ? o0 : (gate == 1) ? o1 : o2;
                        *(float2*)(op + o) = make_float2(r0, r1);
                    }
                }
            }
        }
    }
#undef LDG_A0
#undef STS_A0
#undef STAGE_A1
#undef STAGE_B
}

// ---------------------------------------------------------------------------
// k_final: fc = segsum(fcprod); c = i*g + fc; h = o*tanh(c)
// ---------------------------------------------------------------------------
__global__ void k_final(const float* __restrict__ fcprod, const int* __restrict__ seg,
                        int E, const float* __restrict__ gi, const float* __restrict__ gg,
                        float* __restrict__ out, int P) {
    __shared__ int sb2[2];
    int p = blockIdx.x;
    if (threadIdx.x < 2) {
        int target = p + (int)threadIdx.x;
        int lo = 0, hi = E;
        while (lo < hi) { int m = (lo + hi) >> 1; if (seg[m] < target) lo = m + 1; else hi = m; }
        sb2[threadIdx.x] = lo;
    }
    __syncthreads();
    int lo = sb2[0], hi = sb2[1];
    float fc = 0.0f;
    for (int e = lo; e < hi; ++e) fc += fcprod[(size_t)e * D + threadIdx.x];
    size_t idx = (size_t)p * D + threadIdx.x;
    float c = gi[idx] * gg[idx] + fc;
    float o = out[idx];
    out[(size_t)P * D + idx] = c;
    out[idx] = o * tanhf(c);
}

// ---------------------------------------------------------------------------
extern "C" void kernel_launch(void* const* d_in, const int* in_sizes, int n_in,
                              void* d_out, int out_size) {
    const float* child_hs = (const float*)d_in[0];
    const float* child_cs = (const float*)d_in[1];
    const int*   seg      = (const int*)d_in[2];
    const float* Wg = (const float*)d_in[4];
    const float* bg = (const float*)d_in[5];
    const float* Wf = (const float*)d_in[6];
    const float* bf = (const float*)d_in[7];
    (void)n_in;

    int E = in_sizes[2];
    int P = out_size / (2 * D);
    if (P > MAX_P) P = MAX_P;
    if (E > MAX_E) E = MAX_E;

    float* out = (float*)d_out;

    static bool inited = false;
    static float *fcp_p, *ia_p, *ga_p;
    static __nv_bfloat16 *hshi_p, *hslo_p, *wfh_p, *wfl_p, *wgh_p, *wgl_p;
    if (!inited) {
        cudaGetSymbolAddress((void**)&fcp_p,  g_fcprod);
        cudaGetSymbolAddress((void**)&ia_p,   g_iact);
        cudaGetSymbolAddress((void**)&ga_p,   g_gact);
        cudaGetSymbolAddress((void**)&hshi_p, g_hshi);
        cudaGetSymbolAddress((void**)&hslo_p, g_hslo);
        cudaGetSymbolAddress((void**)&wfh_p,  g_wf_hi);
        cudaGetSymbolAddress((void**)&wfl_p,  g_wf_lo);
        cudaGetSymbolAddress((void**)&wgh_p,  g_wg_hi);
        cudaGetSymbolAddress((void**)&wgl_p,  g_wg_lo);
        cudaFuncSetAttribute(k_gemm<0>, cudaFuncAttributeMaxDynamicSharedMemorySize, SM_TOTAL);
        cudaFuncSetAttribute(k_gemm<1>, cudaFuncAttributeMaxDynamicSharedMemorySize, SM_TOTAL);
        inited = true;
    }

    // weight transpose + bf16 split
    k_wsplit<<<dim3(D / 32, D / 32), 256>>>(Wf, D, wfh_p, wfl_p);
    k_wsplit<<<dim3(D3 / 32, D / 32), 256>>>(Wg, D3, wgh_p, wgl_p);

    // segment sum of child_hs -> bf16 hi/lo
    k_hs_sum<<<P, 256>>>(child_hs, seg, E, hshi_p, hslo_p);

    // fGEMM: per-edge sigmoid(hs@Wf^T + bf) * cs -> fcprod
    k_gemm<0><<<(E + 63) / 64, 256, SM_TOTAL>>>(
        child_hs, nullptr, nullptr, wfh_p, wfl_p, bf, child_cs,
        fcp_p, nullptr, nullptr, E);

    // gates GEMM: hs_sum@Wg^T + bg; gate 0 -> sig(i), 1 -> sig(o) into out_h, 2 -> tanh(g)
    k_gemm<1><<<dim3((P + 63) / 64, 3), 256, SM_TOTAL>>>(
        nullptr, hshi_p, hslo_p, wgh_p, wgl_p, bg, nullptr,
        ia_p, out, ga_p, P);

    // final: fc segsum + LSTM combine
    k_final<<<P, 256>>>(fcp_p, seg, E, ia_p, ga_p, out, P);
}

// round 4
// speedup vs baseline: 3.3441x; 1.2593x over previous
#include <cuda_runtime.h>
#include <cuda_bf16.h>
#include <math.h>
#include <stdint.h>

// TreeLSTM — round 4: HMMA bf16-split, warp tile 64x32, x4 B-ldsm,
// atomic-fused fc segment reduce (no per-edge fcprod buffer).
//
//  k_wsplit : W_f, W_gates -> transposed [N][K] bf16 hi/lo
//  k_hs_sum : per-parent segment sum of child_hs -> bf16 hi/lo [P][256]
//  k_gemm<0>: fc[seg[e]] += sigmoid(child_hs@W_f^T + b_f) * child_cs   (atomic)
//  k_gemm<1>: gates: sig(i)->g_iact, sig(o)->out_h, tanh(g)->g_gact
//  k_final  : c = i*g + fc; h = o*tanh(c)   (elementwise)

#define D    256
#define D3   768
#define MAX_P 100000

// ---------------- scratch (static __device__, no allocation) ----------------
__device__ float g_fc[(size_t)MAX_P * D];
__device__ float g_iact[(size_t)MAX_P * D];
__device__ float g_gact[(size_t)MAX_P * D];
__device__ __nv_bfloat16 g_hshi[(size_t)MAX_P * D];
__device__ __nv_bfloat16 g_hslo[(size_t)MAX_P * D];
__device__ __nv_bfloat16 g_wf_hi[D * D];
__device__ __nv_bfloat16 g_wf_lo[D * D];
__device__ __nv_bfloat16 g_wg_hi[D3 * D];
__device__ __nv_bfloat16 g_wg_lo[D3 * D];

// ---------------- helpers ----------------
__device__ __forceinline__ uint32_t smem_to_u32(const void* p) {
    uint32_t a;
    asm("{ .reg .u64 t; cvta.to.shared.u64 t, %1; cvt.u32.u64 %0, t; }" : "=r"(a) : "l"(p));
    return a;
}
__device__ __forceinline__ float sigmoid_f(float x) { return 1.0f / (1.0f + __expf(-x)); }
__device__ __forceinline__ uint32_t pack_bf16(__nv_bfloat16 a, __nv_bfloat16 b) {
    return (uint32_t)__bfloat16_as_ushort(a) | ((uint32_t)__bfloat16_as_ushort(b) << 16);
}

#define CP_ASYNC16(dst, src) \
    asm volatile("cp.async.cg.shared.global [%0], [%1], 16;" :: "r"(dst), "l"(src))
#define CP_COMMIT() asm volatile("cp.async.commit_group;")
#define CP_WAIT_ALL() asm volatile("cp.async.wait_group 0;")

__device__ __forceinline__ void ldsm_x4(uint32_t a[4], uint32_t addr) {
    asm volatile("ldmatrix.sync.aligned.m8n8.x4.shared.b16 {%0,%1,%2,%3}, [%4];"
        : "=r"(a[0]), "=r"(a[1]), "=r"(a[2]), "=r"(a[3]) : "r"(addr));
}
__device__ __forceinline__ void mma_bf16(float c[4], const uint32_t a[4], const uint32_t b[2]) {
    asm volatile(
        "mma.sync.aligned.m16n8k16.row.col.f32.bf16.bf16.f32 "
        "{%0,%1,%2,%3}, {%4,%5,%6,%7}, {%8,%9}, {%0,%1,%2,%3};"
        : "+f"(c[0]), "+f"(c[1]), "+f"(c[2]), "+f"(c[3])
        : "r"(a[0]), "r"(a[1]), "r"(a[2]), "r"(a[3]), "r"(b[0]), "r"(b[1]));
}

// Swizzled byte offset in a [rows][32 bf16] tile (64B rows, 4 x 16B chunks).
__device__ __forceinline__ uint32_t swz(int row, int ch) {
    return (uint32_t)(row * 64 + ((ch ^ ((row >> 1) & 3)) << 4));
}

// ---------------------------------------------------------------------------
// k_wsplit: W[256 x ncols] row-major -> T_hi/T_lo [ncols][256] bf16
// ---------------------------------------------------------------------------
__global__ void k_wsplit(const float* __restrict__ W, int ncols,
                         __nv_bfloat16* __restrict__ Thi,
                         __nv_bfloat16* __restrict__ Tlo) {
    __shared__ float s[32][33];
    int nt = blockIdx.x * 32, kt = blockIdx.y * 32;
    int tx = threadIdx.x & 31, ty = threadIdx.x >> 5;
    #pragma unroll
    for (int i = 0; i < 4; ++i)
        s[ty + i * 8][tx] = W[(size_t)(kt + ty + i * 8) * ncols + nt + tx];
    __syncthreads();
    #pragma unroll
    for (int i = 0; i < 4; ++i) {
        int n = nt + ty + i * 8;
        int k = kt + tx;
        float x = s[tx][ty + i * 8];
        __nv_bfloat16 hi = __float2bfloat16_rn(x);
        __nv_bfloat16 lo = __float2bfloat16_rn(x - __bfloat162float(hi));
        Thi[(size_t)n * D + k] = hi;
        Tlo[(size_t)n * D + k] = lo;
    }
}

// ---------------------------------------------------------------------------
// k_hs_sum: per-parent segment sum of child_hs -> bf16 hi/lo
// ---------------------------------------------------------------------------
__global__ void k_hs_sum(const float* __restrict__ hs, const int* __restrict__ seg,
                         int E, __nv_bfloat16* __restrict__ ohi,
                         __nv_bfloat16* __restrict__ olo) {
    __shared__ int sb2[2];
    int p = blockIdx.x;
    if (threadIdx.x < 2) {
        int target = p + (int)threadIdx.x;
        int lo = 0, hi = E;
        while (lo < hi) { int m = (lo + hi) >> 1; if (seg[m] < target) lo = m + 1; else hi = m; }
        sb2[threadIdx.x] = lo;
    }
    __syncthreads();
    int lo = sb2[0], hi = sb2[1];
    float s = 0.0f;
    for (int e = lo; e < hi; ++e) s += hs[(size_t)e * D + threadIdx.x];
    __nv_bfloat16 h = __float2bfloat16_rn(s);
    __nv_bfloat16 l = __float2bfloat16_rn(s - __bfloat162float(h));
    ohi[(size_t)p * D + threadIdx.x] = h;
    olo[(size_t)p * D + threadIdx.x] = l;
}

// ---------------------------------------------------------------------------
// k_gemm<MODE>: HMMA bf16-split GEMM. CTA tile M=128 x N=128, BK=32, 8 chunks.
// 8 warps as 2(m) x 4(n); warp tile 64x32; B frags via ldmatrix.x4.
// blockIdx.x: MODE0 -> nhalf (0..1); MODE1 -> gate*2 + nhalf (0..5).
// blockIdx.y: M tile.
// MODE 0: A fp32 inline-split; epilogue atomicAdd fc[seg[row]] += sig(v)*cc.
// MODE 1: A bf16 hi/lo; epilogue per-gate activation stores.
// ---------------------------------------------------------------------------
#define SM_AHI 0
#define SM_ALO 8192
#define SM_BHI 16384
#define SM_BLO 24576
#define SM_STAGE 32768
#define SM_TOTAL 65536

template <int MODE>
__global__ void __launch_bounds__(256, 2)
k_gemm(const float* __restrict__ A32,
       const __nv_bfloat16* __restrict__ Ahi_g,
       const __nv_bfloat16* __restrict__ Alo_g,
       const __nv_bfloat16* __restrict__ Bhi_g,
       const __nv_bfloat16* __restrict__ Blo_g,
       const float* __restrict__ bias_g,
       const float* __restrict__ cc,
       const int* __restrict__ seg,
       float* __restrict__ fc,
       float* __restrict__ o0, float* __restrict__ o1, float* __restrict__ o2,
       int Mtot) {
    extern __shared__ char smem[];
    const uint32_t sb = smem_to_u32(smem);
    const int tid  = threadIdx.x;
    const int lane = tid & 31;
    const int wid  = tid >> 5;
    const int wm   = wid >> 2;          // 0..1
    const int wn   = wid & 3;           // 0..3
    const int bm   = blockIdx.y * 128;
    const int gate  = (MODE == 1) ? ((int)blockIdx.x >> 1) : 0;
    const int nhalf = (MODE == 1) ? ((int)blockIdx.x & 1) : (int)blockIdx.x;

    const __nv_bfloat16* Bhi = Bhi_g + ((size_t)gate * 256 + nhalf * 128) * D;
    const __nv_bfloat16* Blo = Blo_g + ((size_t)gate * 256 + nhalf * 128) * D;
    const float* bias = bias_g + gate * 256 + nhalf * 128;

    float acc[4][4][4];
    #pragma unroll
    for (int i = 0; i < 4; ++i)
        #pragma unroll
        for (int j = 0; j < 4; ++j)
            #pragma unroll
            for (int q = 0; q < 4; ++q) acc[i][j][q] = 0.f;

    // staging geometry: 128 rows x 4 chunks of 16B; 256 threads -> 2 iters
    const int arow0 = tid >> 2, achk = tid & 3;
    const int arow1 = arow0 + 64;
    const int arg0 = min(bm + arow0, Mtot - 1);
    const int arg1 = min(bm + arow1, Mtot - 1);
    const uint32_t aoff0 = swz(arow0, achk);
    const uint32_t aoff1 = swz(arow1, achk);

    float4 af[2][2];

#define LDG_A0(kc) do { \
        const float* _p0 = A32 + (size_t)arg0 * D + (kc) * 32 + achk * 8; \
        const float* _p1 = A32 + (size_t)arg1 * D + (kc) * 32 + achk * 8; \
        af[0][0] = *(const float4*)_p0; af[0][1] = *(const float4*)(_p0 + 4); \
        af[1][0] = *(const float4*)_p1; af[1][1] = *(const float4*)(_p1 + 4); \
    } while (0)

#define STS_A0(buf) do { \
        _Pragma("unroll") \
        for (int _i = 0; _i < 2; ++_i) { \
            float4 v0 = af[_i][0], v1 = af[_i][1]; \
            __nv_bfloat16 h0 = __float2bfloat16_rn(v0.x), h1 = __float2bfloat16_rn(v0.y); \
            __nv_bfloat16 h2 = __float2bfloat16_rn(v0.z), h3 = __float2bfloat16_rn(v0.w); \
            __nv_bfloat16 h4 = __float2bfloat16_rn(v1.x), h5 = __float2bfloat16_rn(v1.y); \
            __nv_bfloat16 h6 = __float2bfloat16_rn(v1.z), h7 = __float2bfloat16_rn(v1.w); \
            __nv_bfloat16 l0 = __float2bfloat16_rn(v0.x - __bfloat162float(h0)); \
            __nv_bfloat16 l1 = __float2bfloat16_rn(v0.y - __bfloat162float(h1)); \
            __nv_bfloat16 l2 = __float2bfloat16_rn(v0.z - __bfloat162float(h2)); \
            __nv_bfloat16 l3 = __float2bfloat16_rn(v0.w - __bfloat162float(h3)); \
            __nv_bfloat16 l4 = __float2bfloat16_rn(v1.x - __bfloat162float(h4)); \
            __nv_bfloat16 l5 = __float2bfloat16_rn(v1.y - __bfloat162float(h5)); \
            __nv_bfloat16 l6 = __float2bfloat16_rn(v1.z - __bfloat162float(h6)); \
            __nv_bfloat16 l7 = __float2bfloat16_rn(v1.w - __bfloat162float(h7)); \
            uint4 uh = make_uint4(pack_bf16(h0,h1), pack_bf16(h2,h3), pack_bf16(h4,h5), pack_bf16(h6,h7)); \
            uint4 ul = make_uint4(pack_bf16(l0,l1), pack_bf16(l2,l3), pack_bf16(l4,l5), pack_bf16(l6,l7)); \
            uint32_t _o = _i ? aoff1 : aoff0; \
            *(uint4*)(smem + (buf) + SM_AHI + _o) = uh; \
            *(uint4*)(smem + (buf) + SM_ALO + _o) = ul; \
        } \
    } while (0)

#define STAGE_A1(kc, buf) do { \
        CP_ASYNC16(sb + (buf) + SM_AHI + aoff0, Ahi_g + (size_t)arg0 * D + (kc) * 32 + achk * 8); \
        CP_ASYNC16(sb + (buf) + SM_ALO + aoff0, Alo_g + (size_t)arg0 * D + (kc) * 32 + achk * 8); \
        CP_ASYNC16(sb + (buf) + SM_AHI + aoff1, Ahi_g + (size_t)arg1 * D + (kc) * 32 + achk * 8); \
        CP_ASYNC16(sb + (buf) + SM_ALO + aoff1, Alo_g + (size_t)arg1 * D + (kc) * 32 + achk * 8); \
    } while (0)

#define STAGE_B(kc, buf) do { \
        CP_ASYNC16(sb + (buf) + SM_BHI + aoff0, Bhi + (size_t)arow0 * D + (kc) * 32 + achk * 8); \
        CP_ASYNC16(sb + (buf) + SM_BLO + aoff0, Blo + (size_t)arow0 * D + (kc) * 32 + achk * 8); \
        CP_ASYNC16(sb + (buf) + SM_BHI + aoff1, Bhi + (size_t)arow1 * D + (kc) * 32 + achk * 8); \
        CP_ASYNC16(sb + (buf) + SM_BLO + aoff1, Blo + (size_t)arow1 * D + (kc) * 32 + achk * 8); \
    } while (0)

    // preamble
    if (MODE == 0) { LDG_A0(0); } else { STAGE_A1(0, 0); }
    STAGE_B(0, 0);
    CP_COMMIT();
    if (MODE == 0) STS_A0(0);
    CP_WAIT_ALL();
    __syncthreads();

    // fragment addressing
    const int arl = lane & 15, ahf = lane >> 4;              // A rows / k-half
    const int brow = (lane & 7) + ((lane >> 4) << 3);        // B: n row (+8 for hi lanes)
    const int bhf = (lane >> 3) & 1;                         // B: k-half

    for (int kc = 0; kc < 8; ++kc) {
        const uint32_t buf  = (uint32_t)((kc & 1) * SM_STAGE);
        const uint32_t nbuf = (uint32_t)(((kc + 1) & 1) * SM_STAGE);
        if (kc < 7) {
            if (MODE == 0) { LDG_A0(kc + 1); } else { STAGE_A1(kc + 1, nbuf); }
            STAGE_B(kc + 1, nbuf);
            CP_COMMIT();
        }
        {
            const uint32_t base = sb + buf;
            uint32_t ah[4][4], al[4][4], bh[2][4], bl[2][4];
            #pragma unroll
            for (int s = 0; s < 2; ++s) {
                #pragma unroll
                for (int mf = 0; mf < 4; ++mf) {
                    int r = wm * 64 + mf * 16 + arl;
                    int ch = s * 2 + ahf;
                    uint32_t o = swz(r, ch);
                    ldsm_x4(ah[mf], base + SM_AHI + o);
                    ldsm_x4(al[mf], base + SM_ALO + o);
                }
                #pragma unroll
                for (int nb = 0; nb < 2; ++nb) {
                    int r = wn * 32 + nb * 16 + brow;
                    int ch = s * 2 + bhf;
                    uint32_t o = swz(r, ch);
                    ldsm_x4(bh[nb], base + SM_BHI + o);
                    ldsm_x4(bl[nb], base + SM_BLO + o);
                }
                #pragma unroll
                for (int mf = 0; mf < 4; ++mf)
                    #pragma unroll
                    for (int nf = 0; nf < 4; ++nf)
                        mma_bf16(acc[mf][nf], ah[mf], &bh[nf >> 1][(nf & 1) * 2]);
                #pragma unroll
                for (int mf = 0; mf < 4; ++mf)
                    #pragma unroll
                    for (int nf = 0; nf < 4; ++nf)
                        mma_bf16(acc[mf][nf], al[mf], &bh[nf >> 1][(nf & 1) * 2]);
                #pragma unroll
                for (int mf = 0; mf < 4; ++mf)
                    #pragma unroll
                    for (int nf = 0; nf < 4; ++nf)
                        mma_bf16(acc[mf][nf], ah[mf], &bl[nf >> 1][(nf & 1) * 2]);
            }
        }
        if (MODE == 0 && kc < 7) STS_A0(nbuf);
        CP_WAIT_ALL();
        __syncthreads();
    }

    // epilogue
    float2 bias2[4];
    #pragma unroll
    for (int nf = 0; nf < 4; ++nf)
        bias2[nf] = *(const float2*)(bias + wn * 32 + nf * 8 + 2 * (lane & 3));

    #pragma unroll
    for (int mf = 0; mf < 4; ++mf) {
        #pragma unroll
        for (int half = 0; half < 2; ++half) {
            int r = bm + wm * 64 + mf * 16 + (lane >> 2) + half * 8;
            bool ok = r < Mtot;
            int sid = (MODE == 0 && ok) ? seg[r] : 0;
            #pragma unroll
            for (int nf = 0; nf < 4; ++nf) {
                int cn = nhalf * 128 + wn * 32 + nf * 8 + 2 * (lane & 3);
                float v0 = acc[mf][nf][half * 2 + 0] + bias2[nf].x;
                float v1 = acc[mf][nf][half * 2 + 1] + bias2[nf].y;
                if (!ok) continue;
                size_t o = (size_t)r * D + cn;
                if (MODE == 0) {
                    float2 ccv = *(const float2*)(cc + o);
                    float* dst = fc + (size_t)sid * D + cn;
                    atomicAdd(dst,     sigmoid_f(v0) * ccv.x);
                    atomicAdd(dst + 1, sigmoid_f(v1) * ccv.y);
                } else {
                    float r0, r1;
                    if (gate == 2) { r0 = tanhf(v0); r1 = tanhf(v1); }
                    else           { r0 = sigmoid_f(v0); r1 = sigmoid_f(v1); }
                    float* op = (gate == 0) ? o0 : (gate == 1) ? o1 : o2;
                    *(float2*)(op + o) = make_float2(r0, r1);
                }
            }
        }
    }
#undef LDG_A0
#undef STS_A0
#undef STAGE_A1
#undef STAGE_B
}

// ---------------------------------------------------------------------------
// k_final: c = i*g + fc; h = o*tanh(c)  (elementwise, float4)
// ---------------------------------------------------------------------------
__global__ void k_final(const float* __restrict__ fc, const float* __restrict__ gi,
                        const float* __restrict__ gg, float* __restrict__ out,
                        int total) {  // total = P*D (multiple of 4)
    int i4 = blockIdx.x * blockDim.x + threadIdx.x;
    if (i4 * 4 < total) {
        size_t idx = (size_t)i4 * 4;
        float4 vi = *(const float4*)(gi + idx);
        float4 vg = *(const float4*)(gg + idx);
        float4 vf = *(const float4*)(fc + idx);
        float4 vo = *(const float4*)(out + idx);
        float4 c = make_float4(vi.x * vg.x + vf.x, vi.y * vg.y + vf.y,
                               vi.z * vg.z + vf.z, vi.w * vg.w + vf.w);
        float4 h = make_float4(vo.x * tanhf(c.x), vo.y * tanhf(c.y),
                               vo.z * tanhf(c.z), vo.w * tanhf(c.w));
        *(float4*)(out + (size_t)total + idx) = c;
        *(float4*)(out + idx) = h;
    }
}

// ---------------------------------------------------------------------------
extern "C" void kernel_launch(void* const* d_in, const int* in_sizes, int n_in,
                              void* d_out, int out_size) {
    const float* child_hs = (const float*)d_in[0];
    const float* child_cs = (const float*)d_in[1];
    const int*   seg      = (const int*)d_in[2];
    const float* Wg = (const float*)d_in[4];
    const float* bg = (const float*)d_in[5];
    const float* Wf = (const float*)d_in[6];
    const float* bf = (const float*)d_in[7];
    (void)n_in;

    int E = in_sizes[2];
    int P = out_size / (2 * D);
    if (P > MAX_P) P = MAX_P;

    float* out = (float*)d_out;

    static bool inited = false;
    static float *fc_p, *ia_p, *ga_p;
    static __nv_bfloat16 *hshi_p, *hslo_p, *wfh_p, *wfl_p, *wgh_p, *wgl_p;
    if (!inited) {
        cudaGetSymbolAddress((void**)&fc_p,   g_fc);
        cudaGetSymbolAddress((void**)&ia_p,   g_iact);
        cudaGetSymbolAddress((void**)&ga_p,   g_gact);
        cudaGetSymbolAddress((void**)&hshi_p, g_hshi);
        cudaGetSymbolAddress((void**)&hslo_p, g_hslo);
        cudaGetSymbolAddress((void**)&wfh_p,  g_wf_hi);
        cudaGetSymbolAddress((void**)&wfl_p,  g_wf_lo);
        cudaGetSymbolAddress((void**)&wgh_p,  g_wg_hi);
        cudaGetSymbolAddress((void**)&wgl_p,  g_wg_lo);
        cudaFuncSetAttribute(k_gemm<0>, cudaFuncAttributeMaxDynamicSharedMemorySize, SM_TOTAL);
        cudaFuncSetAttribute(k_gemm<1>, cudaFuncAttributeMaxDynamicSharedMemorySize, SM_TOTAL);
        inited = true;
    }

    // weight transpose + bf16 split
    k_wsplit<<<dim3(D / 32, D / 32), 256>>>(Wf, D, wfh_p, wfl_p);
    k_wsplit<<<dim3(D3 / 32, D / 32), 256>>>(Wg, D3, wgh_p, wgl_p);

    // zero fc accumulator (graph-capturable)
    cudaMemsetAsync(fc_p, 0, (size_t)P * D * sizeof(float), 0);

    // segment sum of child_hs -> bf16 hi/lo
    k_hs_sum<<<P, 256>>>(child_hs, seg, E, hshi_p, hslo_p);

    // fGEMM: fc[seg[e]] += sigmoid(hs@Wf^T + bf) * cs  (atomic epilogue)
    k_gemm<0><<<dim3(2, (E + 127) / 128), 256, SM_TOTAL>>>(
        child_hs, nullptr, nullptr, wfh_p, wfl_p, bf, child_cs, seg, fc_p,
        nullptr, nullptr, nullptr, E);

    // gates GEMM: gate 0 -> sig(i), 1 -> sig(o) into out_h, 2 -> tanh(g)
    k_gemm<1><<<dim3(6, (P + 127) / 128), 256, SM_TOTAL>>>(
        nullptr, hshi_p, hslo_p, wgh_p, wgl_p, bg, nullptr, nullptr, nullptr,
        ia_p, out, ga_p, P);

    // final elementwise combine
    k_final<<<(P * D / 4 + 255) / 256, 256>>>(fc_p, ia_p, ga_p, out, P * D);
}

// round 5
// speedup vs baseline: 3.7570x; 1.1235x over previous
#include <cuda_runtime.h>
#include <cuda_bf16.h>
#include <math.h>
#include <stdint.h>

// TreeLSTM — round 5: single-pass TF32 HMMA + 3-stage cp.async pipeline.
//
//  k_wsplit : W_f, W_gates -> transposed [N][K] fp32 (tf32-rounded)
//  k_hs_sum : per-parent segment sum of child_hs -> fp32 [P][256]
//  k_gemm<0>: fc[seg[e]] += sigmoid(child_hs@W_f^T + b_f) * child_cs  (atomic)
//  k_gemm<1>: gates: sig(i)->g_iact, sig(o)->out_h, tanh(g)->g_gact
//  k_final  : c = i*g + fc; h = o*tanh(c)

#define D    256
#define D3   768
#define MAX_P 100000

// ---------------- scratch (static __device__, no allocation) ----------------
__device__ float g_fc[(size_t)MAX_P * D];
__device__ float g_iact[(size_t)MAX_P * D];
__device__ float g_gact[(size_t)MAX_P * D];
__device__ float g_hs_sum[(size_t)MAX_P * D];
__device__ float g_wf_t[D * D];     // tf32-rounded, [N][K]
__device__ float g_wg_t[D3 * D];    // tf32-rounded, [N][K]

// ---------------- helpers ----------------
__device__ __forceinline__ uint32_t smem_to_u32(const void* p) {
    uint32_t a;
    asm("{ .reg .u64 t; cvta.to.shared.u64 t, %1; cvt.u32.u64 %0, t; }" : "=r"(a) : "l"(p));
    return a;
}
__device__ __forceinline__ float sigmoid_f(float x) { return 1.0f / (1.0f + __expf(-x)); }
__device__ __forceinline__ float tf32_round(float x) {
    uint32_t r;
    asm("cvt.rna.tf32.f32 %0, %1;" : "=r"(r) : "f"(x));
    return __uint_as_float(r);
}
__device__ __forceinline__ uint32_t tf32_u(uint32_t x) {
    uint32_t r;
    asm("cvt.rna.tf32.f32 %0, %1;" : "=r"(r) : "f"(__uint_as_float(x)));
    return r;
}

#define CP_ASYNC16(dst, src) \
    asm volatile("cp.async.cg.shared.global [%0], [%1], 16;" :: "r"(dst), "l"(src))
#define CP_COMMIT() asm volatile("cp.async.commit_group;")
#define CP_WAIT_1() asm volatile("cp.async.wait_group 1;")

__device__ __forceinline__ void ldsm_x4(uint32_t a[4], uint32_t addr) {
    asm volatile("ldmatrix.sync.aligned.m8n8.x4.shared.b16 {%0,%1,%2,%3}, [%4];"
        : "=r"(a[0]), "=r"(a[1]), "=r"(a[2]), "=r"(a[3]) : "r"(addr));
}
__device__ __forceinline__ void mma_tf32(float c[4], const uint32_t a[4], const uint32_t b[2]) {
    asm volatile(
        "mma.sync.aligned.m16n8k8.row.col.f32.tf32.tf32.f32 "
        "{%0,%1,%2,%3}, {%4,%5,%6,%7}, {%8,%9}, {%0,%1,%2,%3};"
        : "+f"(c[0]), "+f"(c[1]), "+f"(c[2]), "+f"(c[3])
        : "r"(a[0]), "r"(a[1]), "r"(a[2]), "r"(a[3]), "r"(b[0]), "r"(b[1]));
}

// Swizzled byte offset in a [rows][32 f32] tile: 128B rows, 8 chunks of 16B.
// ch ^= row&7 -> 8 consecutive rows hit 8 distinct 16B slots (ldmatrix clean).
__device__ __forceinline__ uint32_t swz8(int row, int ch) {
    return (uint32_t)(row * 128 + (((ch) ^ ((row) & 7)) << 4));
}

// ---------------------------------------------------------------------------
// k_wsplit: W[256 x ncols] row-major -> T [ncols][256] fp32 (tf32-rounded)
// ---------------------------------------------------------------------------
__global__ void k_wsplit(const float* __restrict__ W, int ncols,
                         float* __restrict__ T) {
    __shared__ float s[32][33];
    int nt = blockIdx.x * 32, kt = blockIdx.y * 32;
    int tx = threadIdx.x & 31, ty = threadIdx.x >> 5;
    #pragma unroll
    for (int i = 0; i < 4; ++i)
        s[ty + i * 8][tx] = W[(size_t)(kt + ty + i * 8) * ncols + nt + tx];
    __syncthreads();
    #pragma unroll
    for (int i = 0; i < 4; ++i) {
        int n = nt + ty + i * 8;
        int k = kt + tx;
        T[(size_t)n * D + k] = tf32_round(s[tx][ty + i * 8]);
    }
}

// ---------------------------------------------------------------------------
// k_hs_sum: per-parent segment sum of child_hs -> fp32
// ---------------------------------------------------------------------------
__global__ void k_hs_sum(const float* __restrict__ hs, const int* __restrict__ seg,
                         int E, float* __restrict__ out) {
    __shared__ int sb2[2];
    int p = blockIdx.x;
    if (threadIdx.x < 2) {
        int target = p + (int)threadIdx.x;
        int lo = 0, hi = E;
        while (lo < hi) { int m = (lo + hi) >> 1; if (seg[m] < target) lo = m + 1; else hi = m; }
        sb2[threadIdx.x] = lo;
    }
    __syncthreads();
    int lo = sb2[0], hi = sb2[1];
    float s = 0.0f;
    for (int e = lo; e < hi; ++e) s += hs[(size_t)e * D + threadIdx.x];
    out[(size_t)p * D + threadIdx.x] = s;
}

// ---------------------------------------------------------------------------
// k_gemm<MODE>: TF32 HMMA GEMM. CTA tile M=128 x N=128, BK=32, 8 chunks,
// 3-stage cp.async pipeline. 8 warps as 2(m) x 4(n); warp tile 64x32.
// A fp32 in gmem (cp.async raw, cvt.rna on fragments). B fp32 tf32-rounded.
// blockIdx.x: MODE0 -> nhalf (0..1); MODE1 -> gate*2 + nhalf (0..5).
// MODE 0: epilogue atomicAdd fc[seg[row]] += sigmoid(v)*cc.
// MODE 1: epilogue per-gate activation stores.
// ---------------------------------------------------------------------------
#define SM_A 0
#define SM_B 16384
#define SM_STAGE 32768
#define SM_TOTAL (3 * SM_STAGE)

template <int MODE>
__global__ void __launch_bounds__(256, 2)
k_gemm(const float* __restrict__ A32,
       const float* __restrict__ Bt_g,
       const float* __restrict__ bias_g,
       const float* __restrict__ cc,
       const int* __restrict__ seg,
       float* __restrict__ fc,
       float* __restrict__ o0, float* __restrict__ o1, float* __restrict__ o2,
       int Mtot) {
    extern __shared__ char smem[];
    const uint32_t sb = smem_to_u32(smem);
    const int tid  = threadIdx.x;
    const int lane = tid & 31;
    const int wid  = tid >> 5;
    const int wm   = wid >> 2;          // 0..1
    const int wn   = wid & 3;           // 0..3
    const int bm   = blockIdx.y * 128;
    const int gate  = (MODE == 1) ? ((int)blockIdx.x >> 1) : 0;
    const int nhalf = (MODE == 1) ? ((int)blockIdx.x & 1) : (int)blockIdx.x;

    const float* Bt = Bt_g + ((size_t)gate * 256 + nhalf * 128) * D;
    const float* bias = bias_g + gate * 256 + nhalf * 128;

    float acc[4][4][4];
    #pragma unroll
    for (int i = 0; i < 4; ++i)
        #pragma unroll
        for (int j = 0; j < 4; ++j)
            #pragma unroll
            for (int q = 0; q < 4; ++q) acc[i][j][q] = 0.f;

    // staging: 128 rows x 8 chunks (16B) for each of A and B; 256 thr x 4 iters
    const int srow = tid >> 3;          // 0..31 (+32*it)
    const int sch  = tid & 7;

#define STAGE_AB(kc, slot) do { \
        _Pragma("unroll") \
        for (int _it = 0; _it < 4; ++_it) { \
            int _r = srow + _it * 32; \
            int _ar = min(bm + _r, Mtot - 1); \
            uint32_t _o = swz8(_r, sch); \
            CP_ASYNC16(sb + (slot) + SM_A + _o, A32 + (size_t)_ar * D + (kc) * 32 + sch * 4); \
            CP_ASYNC16(sb + (slot) + SM_B + _o, Bt  + (size_t)_r  * D + (kc) * 32 + sch * 4); \
        } \
    } while (0)

    // prologue: stages 0, 1
    STAGE_AB(0, 0);
    CP_COMMIT();
    STAGE_AB(1, SM_STAGE);
    CP_COMMIT();

    const int l7 = lane & 7;
    const int l8 = (lane >> 3) & 1;
    const int l16 = lane >> 4;

    uint32_t slot = 0;
    #pragma unroll 1
    for (int kc = 0; kc < 8; ++kc) {
        CP_WAIT_1();
        __syncthreads();
        if (kc + 2 < 8) {
            uint32_t ns = (uint32_t)(((kc + 2) % 3) * SM_STAGE);
            STAGE_AB(kc + 2, ns);
        }
        CP_COMMIT();   // one group per iteration keeps wait accounting exact

        const uint32_t base = sb + slot;
        uint32_t ah[4][4], bb[4][4];
        #pragma unroll
        for (int s16 = 0; s16 < 2; ++s16) {
            // B frags: x4 covers k16 for one n8 tile
            #pragma unroll
            for (int nf = 0; nf < 4; ++nf) {
                int r = wn * 32 + nf * 8 + l7;
                int ch = 4 * s16 + (lane >> 3);
                ldsm_x4(bb[nf], base + SM_B + swz8(r, ch));
            }
            #pragma unroll
            for (int h = 0; h < 2; ++h) {
                int kk = 2 * s16 + h;
                #pragma unroll
                for (int mf = 0; mf < 4; ++mf) {
                    int r = wm * 64 + mf * 16 + l8 * 8 + l7;
                    int ch = 2 * kk + l16;
                    ldsm_x4(ah[mf], base + SM_A + swz8(r, ch));
                    ah[mf][0] = tf32_u(ah[mf][0]);
                    ah[mf][1] = tf32_u(ah[mf][1]);
                    ah[mf][2] = tf32_u(ah[mf][2]);
                    ah[mf][3] = tf32_u(ah[mf][3]);
                }
                #pragma unroll
                for (int mf = 0; mf < 4; ++mf)
                    #pragma unroll
                    for (int nf = 0; nf < 4; ++nf)
                        mma_tf32(acc[mf][nf], ah[mf], &bb[nf][2 * h]);
            }
        }
        slot = (slot == 2u * SM_STAGE) ? 0u : slot + SM_STAGE;
    }

    // epilogue
    float2 bias2[4];
    #pragma unroll
    for (int nf = 0; nf < 4; ++nf)
        bias2[nf] = *(const float2*)(bias + wn * 32 + nf * 8 + 2 * (lane & 3));

    #pragma unroll
    for (int mf = 0; mf < 4; ++mf) {
        #pragma unroll
        for (int half = 0; half < 2; ++half) {
            int r = bm + wm * 64 + mf * 16 + (lane >> 2) + half * 8;
            bool ok = r < Mtot;
            int sid = (MODE == 0 && ok) ? seg[r] : 0;
            #pragma unroll
            for (int nf = 0; nf < 4; ++nf) {
                int cn = nhalf * 128 + wn * 32 + nf * 8 + 2 * (lane & 3);
                float v0 = acc[mf][nf][half * 2 + 0] + bias2[nf].x;
                float v1 = acc[mf][nf][half * 2 + 1] + bias2[nf].y;
                if (!ok) continue;
                size_t o = (size_t)r * D + cn;
                if (MODE == 0) {
                    float2 ccv = *(const float2*)(cc + o);
                    float* dst = fc + (size_t)sid * D + cn;
                    atomicAdd(dst,     sigmoid_f(v0) * ccv.x);
                    atomicAdd(dst + 1, sigmoid_f(v1) * ccv.y);
                } else {
                    float r0, r1;
                    if (gate == 2) { r0 = tanhf(v0); r1 = tanhf(v1); }
                    else           { r0 = sigmoid_f(v0); r1 = sigmoid_f(v1); }
                    float* op = (gate == 0) ? o0 : (gate == 1) ? o1 : o2;
                    *(float2*)(op + o) = make_float2(r0, r1);
                }
            }
        }
    }
#undef STAGE_AB
}

// ---------------------------------------------------------------------------
// k_final: c = i*g + fc; h = o*tanh(c)  (elementwise, float4)
// ---------------------------------------------------------------------------
__global__ void k_final(const float* __restrict__ fc, const float* __restrict__ gi,
                        const float* __restrict__ gg, float* __restrict__ out,
                        int total) {
    int i4 = blockIdx.x * blockDim.x + threadIdx.x;
    if (i4 * 4 < total) {
        size_t idx = (size_t)i4 * 4;
        float4 vi = *(const float4*)(gi + idx);
        float4 vg = *(const float4*)(gg + idx);
        float4 vf = *(const float4*)(fc + idx);
        float4 vo = *(const float4*)(out + idx);
        float4 c = make_float4(vi.x * vg.x + vf.x, vi.y * vg.y + vf.y,
                               vi.z * vg.z + vf.z, vi.w * vg.w + vf.w);
        float4 h = make_float4(vo.x * tanhf(c.x), vo.y * tanhf(c.y),
                               vo.z * tanhf(c.z), vo.w * tanhf(c.w));
        *(float4*)(out + (size_t)total + idx) = c;
        *(float4*)(out + idx) = h;
    }
}

// ---------------------------------------------------------------------------
extern "C" void kernel_launch(void* const* d_in, const int* in_sizes, int n_in,
                              void* d_out, int out_size) {
    const float* child_hs = (const float*)d_in[0];
    const float* child_cs = (const float*)d_in[1];
    const int*   seg      = (const int*)d_in[2];
    const float* Wg = (const float*)d_in[4];
    const float* bg = (const float*)d_in[5];
    const float* Wf = (const float*)d_in[6];
    const float* bf = (const float*)d_in[7];
    (void)n_in;

    int E = in_sizes[2];
    int P = out_size / (2 * D);
    if (P > MAX_P) P = MAX_P;

    float* out = (float*)d_out;

    static bool inited = false;
    static float *fc_p, *ia_p, *ga_p, *hs_p, *wf_p, *wg_p;
    if (!inited) {
        cudaGetSymbolAddress((void**)&fc_p, g_fc);
        cudaGetSymbolAddress((void**)&ia_p, g_iact);
        cudaGetSymbolAddress((void**)&ga_p, g_gact);
        cudaGetSymbolAddress((void**)&hs_p, g_hs_sum);
        cudaGetSymbolAddress((void**)&wf_p, g_wf_t);
        cudaGetSymbolAddress((void**)&wg_p, g_wg_t);
        cudaFuncSetAttribute(k_gemm<0>, cudaFuncAttributeMaxDynamicSharedMemorySize, SM_TOTAL);
        cudaFuncSetAttribute(k_gemm<1>, cudaFuncAttributeMaxDynamicSharedMemorySize, SM_TOTAL);
        inited = true;
    }

    // weight transpose + tf32 rounding
    k_wsplit<<<dim3(D / 32, D / 32), 256>>>(Wf, D, wf_p);
    k_wsplit<<<dim3(D3 / 32, D / 32), 256>>>(Wg, D3, wg_p);

    // zero fc accumulator
    cudaMemsetAsync(fc_p, 0, (size_t)P * D * sizeof(float), 0);

    // segment sum of child_hs
    k_hs_sum<<<P, 256>>>(child_hs, seg, E, hs_p);

    // fGEMM: fc[seg[e]] += sigmoid(hs@Wf^T + bf) * cs
    k_gemm<0><<<dim3(2, (E + 127) / 128), 256, SM_TOTAL>>>(
        child_hs, wf_p, bf, child_cs, seg, fc_p,
        nullptr, nullptr, nullptr, E);

    // gates GEMM: gate 0 -> sig(i), 1 -> sig(o) into out_h, 2 -> tanh(g)
    k_gemm<1><<<dim3(6, (P + 127) / 128), 256, SM_TOTAL>>>(
        hs_p, wg_p, bg, nullptr, nullptr, nullptr,
        ia_p, out, ga_p, P);

    // final elementwise combine
    k_final<<<(P * D / 4 + 255) / 256, 256>>>(fc_p, ia_p, ga_p, out, P * D);
}